// round 6
// baseline (speedup 1.0000x reference)
#include <cuda_runtime.h>
#include <cuda_bf16.h>
#include <math.h>
#include <stdint.h>

#define N_NODES 100000
#define N_EDGES 1600000
#define IN_DIM 768
#define HIDDEN 256
#define N_CLASSES 3

// ---- device scratch (static; no allocation allowed) ----
__device__ float g_dinv[N_NODES];
__device__ float g_h[(size_t)N_NODES * HIDDEN];    // h' = dinv[i] * (x@W1)[i]
__device__ int g_cnt[N_NODES];
__device__ int g_off[N_NODES + 1];
__device__ int g_cur[N_NODES];
__device__ int g_csr[N_EDGES];
__device__ __nv_bfloat16 g_w1t_hi[(size_t)HIDDEN * IN_DIM];  // W1^T split-hi [256][768]
__device__ __nv_bfloat16 g_w1t_lo[(size_t)HIDDEN * IN_DIM];  // W1^T split-lo

// ---------------------------------------------------------------------------
// helpers
// ---------------------------------------------------------------------------
__device__ __forceinline__ uint32_t smem_u32(const void* p) {
    uint32_t a;
    asm("{ .reg .u64 t; cvta.to.shared.u64 t, %1; cvt.u32.u64 %0, t; }" : "=r"(a) : "l"(p));
    return a;
}
__device__ __forceinline__ void mma_bf16(float* d, const uint32_t* a, const uint32_t* b) {
    asm volatile(
        "mma.sync.aligned.m16n8k16.row.col.f32.bf16.bf16.f32 "
        "{%0,%1,%2,%3}, {%4,%5,%6,%7}, {%8,%9}, {%0,%1,%2,%3};"
        : "+f"(d[0]), "+f"(d[1]), "+f"(d[2]), "+f"(d[3])
        : "r"(a[0]), "r"(a[1]), "r"(a[2]), "r"(a[3]), "r"(b[0]), "r"(b[1]));
}
__device__ __forceinline__ void ldmat_x4(uint32_t* r, uint32_t addr) {
    asm volatile("ldmatrix.sync.aligned.m8n8.x4.shared.b16 {%0,%1,%2,%3}, [%4];"
                 : "=r"(r[0]), "=r"(r[1]), "=r"(r[2]), "=r"(r[3]) : "r"(addr));
}
__device__ __forceinline__ uint32_t pack_bf2(__nv_bfloat16 a, __nv_bfloat16 b) {
    return ((uint32_t)__bfloat16_as_ushort(b) << 16) | __bfloat16_as_ushort(a);
}
#define CP_ASYNC16(dst, src) \
    asm volatile("cp.async.ca.shared.global [%0], [%1], 16;" :: "r"(dst), "l"(src))
#define CP_COMMIT() asm volatile("cp.async.commit_group;" ::: "memory")
#define CP_WAIT0()  asm volatile("cp.async.wait_group 0;" ::: "memory")

// ---------------------------------------------------------------------------
// launch #1: W1 prep (transpose + bf16 split) AND zero g_cnt
// ---------------------------------------------------------------------------
__global__ void k_prep_w1(const float* __restrict__ W1) {
    int idx = blockIdx.x * blockDim.x + threadIdx.x;
    if (idx < N_NODES) g_cnt[idx] = 0;
    if (idx >= IN_DIM * HIDDEN) return;
    int k = idx / HIDDEN;
    int nn = idx % HIDDEN;
    float w = W1[idx];
    __nv_bfloat16 hi = __float2bfloat16(w);
    __nv_bfloat16 lo = __float2bfloat16(w - __bfloat162float(hi));
    g_w1t_hi[(size_t)nn * IN_DIM + k] = hi;
    g_w1t_lo[(size_t)nn * IN_DIM + k] = lo;
}

// ---------------------------------------------------------------------------
// launch #2: histogram destination degrees
// ---------------------------------------------------------------------------
__global__ void k_cnt(const int* __restrict__ dst, int E) {
    int i = blockIdx.x * blockDim.x + threadIdx.x;
    if (i < E) atomicAdd(&g_cnt[dst[i]], 1);
}

// ---------------------------------------------------------------------------
// launch #3: single-block scan -> g_off, plus dinv + cur
// ---------------------------------------------------------------------------
__global__ void k_scan(int n) {
    __shared__ int swarp[32];
    __shared__ int carry_s;
    const int t = threadIdx.x;
    const int lane = t & 31;
    const int wid = t >> 5;
    if (t == 0) { carry_s = 0; g_off[0] = 0; }
    __syncthreads();
    for (int base = 0; base < n; base += 1024) {
        int i = base + t;
        int v = (i < n) ? g_cnt[i] : 0;
        int x = v;
#pragma unroll
        for (int o = 1; o < 32; o <<= 1) {
            int u = __shfl_up_sync(0xFFFFFFFFu, x, o);
            if (lane >= o) x += u;
        }
        if (lane == 31) swarp[wid] = x;
        __syncthreads();
        if (wid == 0) {
            int y = swarp[lane];
#pragma unroll
            for (int o = 1; o < 32; o <<= 1) {
                int u = __shfl_up_sync(0xFFFFFFFFu, y, o);
                if (lane >= o) y += u;
            }
            swarp[lane] = y;
        }
        __syncthreads();
        int pre = (wid > 0) ? swarp[wid - 1] : 0;
        int incl = carry_s + pre + x;
        if (i < n) {
            g_off[i + 1] = incl;
            g_cur[i] = incl - v;
            g_dinv[i] = rsqrtf(1.0f + (float)v);
        }
        int total = swarp[31];
        __syncthreads();
        if (t == 0) carry_s += total;
        __syncthreads();
    }
}

// ---------------------------------------------------------------------------
// launch #4 (PROFILED): HMMA GEMM  h' = dinv[row] * (x @ W1)
//   2-way bf16 split, CTA tile 128x256 (full N), warp tile 64x64,
//   K chunks of 32, double-buffered smem, cp.async for B.
// ---------------------------------------------------------------------------
#define AHI_OFF 0
#define ALO_OFF 10240
#define BHI_OFF 20480
#define BLO_OFF 40960
#define SMB 61440
#define GEMM_SMEM (2 * SMB)

extern __shared__ char smem_raw[];

__global__ __launch_bounds__(256) void k_gemm_hmma(const float* __restrict__ x, int n) {
    const uint32_t sb = smem_u32(smem_raw);
    const int tid = threadIdx.x;
    const int wid = tid >> 5;
    const int lane = tid & 31;
    const int wm = wid >> 2;          // 0..1  (x64 rows)
    const int wn = wid & 3;           // 0..3  (x64 cols)
    const int gID = lane >> 2;
    const int tig = lane & 3;
    const int row0 = blockIdx.x * 128;

    float acc[4][8][4];
#pragma unroll
    for (int i = 0; i < 4; i++)
#pragma unroll
        for (int j = 0; j < 8; j++)
#pragma unroll
            for (int q = 0; q < 4; q++) acc[i][j][q] = 0.0f;

    // A staging: 2 threads per row, 16 fp32 each
    const int arow = tid >> 1;
    const int acol = (tid & 1) * 16;
    const int grow = row0 + arow;
    const bool a_ok = (grow < n);
    const float* aptr = x + (size_t)(a_ok ? grow : 0) * IN_DIM + acol;
    const uint32_t a_st = (uint32_t)(arow * 80 + acol * 2);
    // B staging: 1 thread per row (256 rows), 32 halves = 64B
    const __nv_bfloat16* bhptr = g_w1t_hi + (size_t)tid * IN_DIM;
    const __nv_bfloat16* blptr = g_w1t_lo + (size_t)tid * IN_DIM;
    const uint32_t b_st = (uint32_t)(tid * 80);

    // fragment byte offsets
    const uint32_t a_frag = (uint32_t)((lane & 15) * 80 + ((lane & 16) ? 16 : 0));
    const uint32_t b_frag = (uint32_t)(((lane & 7) + ((lane & 16) ? 8 : 0)) * 80 + ((lane & 8) ? 16 : 0));

    // ---- prologue: stage chunk 0 into buffer 0 ----
    {
        float f[16];
#pragma unroll
        for (int j = 0; j < 4; j++) {
            float4 v = a_ok ? *reinterpret_cast<const float4*>(aptr + j * 4)
                            : make_float4(0.f, 0.f, 0.f, 0.f);
            f[j * 4 + 0] = v.x; f[j * 4 + 1] = v.y; f[j * 4 + 2] = v.z; f[j * 4 + 3] = v.w;
        }
        uint32_t hiw[8], low[8];
#pragma unroll
        for (int j = 0; j < 8; j++) {
            __nv_bfloat16 h0 = __float2bfloat16(f[j * 2 + 0]);
            __nv_bfloat16 h1 = __float2bfloat16(f[j * 2 + 1]);
            __nv_bfloat16 l0 = __float2bfloat16(f[j * 2 + 0] - __bfloat162float(h0));
            __nv_bfloat16 l1 = __float2bfloat16(f[j * 2 + 1] - __bfloat162float(h1));
            hiw[j] = pack_bf2(h0, h1);
            low[j] = pack_bf2(l0, l1);
        }
        char* sm = smem_raw;
        *reinterpret_cast<uint4*>(sm + AHI_OFF + a_st)      = make_uint4(hiw[0], hiw[1], hiw[2], hiw[3]);
        *reinterpret_cast<uint4*>(sm + AHI_OFF + a_st + 16) = make_uint4(hiw[4], hiw[5], hiw[6], hiw[7]);
        *reinterpret_cast<uint4*>(sm + ALO_OFF + a_st)      = make_uint4(low[0], low[1], low[2], low[3]);
        *reinterpret_cast<uint4*>(sm + ALO_OFF + a_st + 16) = make_uint4(low[4], low[5], low[6], low[7]);
#pragma unroll
        for (int j = 0; j < 4; j++) {
            CP_ASYNC16(sb + BHI_OFF + b_st + j * 16, bhptr + j * 8);
            CP_ASYNC16(sb + BLO_OFF + b_st + j * 16, blptr + j * 8);
        }
        CP_COMMIT();
    }
    CP_WAIT0();
    __syncthreads();

    int buf = 0;
    for (int c = 0; c < IN_DIM / 32; c++) {
        const bool has_next = (c + 1 < IN_DIM / 32);
        float f[16];
        if (has_next) {
            const int k1 = (c + 1) * 32;
            const uint32_t nb = (uint32_t)((buf ^ 1) * SMB);
#pragma unroll
            for (int j = 0; j < 4; j++) {
                CP_ASYNC16(sb + nb + BHI_OFF + b_st + j * 16, bhptr + k1 + j * 8);
                CP_ASYNC16(sb + nb + BLO_OFF + b_st + j * 16, blptr + k1 + j * 8);
            }
            CP_COMMIT();
#pragma unroll
            for (int j = 0; j < 4; j++) {
                float4 v = a_ok ? *reinterpret_cast<const float4*>(aptr + k1 + j * 4)
                                : make_float4(0.f, 0.f, 0.f, 0.f);
                f[j * 4 + 0] = v.x; f[j * 4 + 1] = v.y; f[j * 4 + 2] = v.z; f[j * 4 + 3] = v.w;
            }
        }

        // ---- compute current buffer: 2 k-steps of 16 ----
        const uint32_t bb = sb + (uint32_t)(buf * SMB);
#pragma unroll
        for (int kk2 = 0; kk2 < 2; kk2++) {
            const uint32_t kkb = kk2 * 32;
            uint32_t bh[8][2], bl[8][2];
#pragma unroll
            for (int p = 0; p < 4; p++) {
                uint32_t r[4];
                ldmat_x4(r, bb + BHI_OFF + (uint32_t)(wn * 64 + p * 16) * 80 + kkb + b_frag);
                bh[2 * p][0] = r[0]; bh[2 * p][1] = r[1]; bh[2 * p + 1][0] = r[2]; bh[2 * p + 1][1] = r[3];
                ldmat_x4(r, bb + BLO_OFF + (uint32_t)(wn * 64 + p * 16) * 80 + kkb + b_frag);
                bl[2 * p][0] = r[0]; bl[2 * p][1] = r[1]; bl[2 * p + 1][0] = r[2]; bl[2 * p + 1][1] = r[3];
            }
#pragma unroll
            for (int mf = 0; mf < 4; mf++) {
                uint32_t ah[4], al[4];
                const uint32_t aro = (uint32_t)(wm * 64 + mf * 16) * 80 + kkb;
                ldmat_x4(ah, bb + AHI_OFF + aro + a_frag);
                ldmat_x4(al, bb + ALO_OFF + aro + a_frag);
#pragma unroll
                for (int nf = 0; nf < 8; nf++) {
                    mma_bf16(acc[mf][nf], ah, bh[nf]);
                    mma_bf16(acc[mf][nf], ah, bl[nf]);
                    mma_bf16(acc[mf][nf], al, bh[nf]);
                }
            }
        }

        // ---- stage A into next buffer ----
        if (has_next) {
            uint32_t hiw[8], low[8];
#pragma unroll
            for (int j = 0; j < 8; j++) {
                __nv_bfloat16 h0 = __float2bfloat16(f[j * 2 + 0]);
                __nv_bfloat16 h1 = __float2bfloat16(f[j * 2 + 1]);
                __nv_bfloat16 l0 = __float2bfloat16(f[j * 2 + 0] - __bfloat162float(h0));
                __nv_bfloat16 l1 = __float2bfloat16(f[j * 2 + 1] - __bfloat162float(h1));
                hiw[j] = pack_bf2(h0, h1);
                low[j] = pack_bf2(l0, l1);
            }
            char* sm = smem_raw + (buf ^ 1) * SMB;
            *reinterpret_cast<uint4*>(sm + AHI_OFF + a_st)      = make_uint4(hiw[0], hiw[1], hiw[2], hiw[3]);
            *reinterpret_cast<uint4*>(sm + AHI_OFF + a_st + 16) = make_uint4(hiw[4], hiw[5], hiw[6], hiw[7]);
            *reinterpret_cast<uint4*>(sm + ALO_OFF + a_st)      = make_uint4(low[0], low[1], low[2], low[3]);
            *reinterpret_cast<uint4*>(sm + ALO_OFF + a_st + 16) = make_uint4(low[4], low[5], low[6], low[7]);
        }
        CP_WAIT0();
        __syncthreads();
        buf ^= 1;
    }

    // ---- epilogue: scale by dinv, store g_h ----
#pragma unroll
    for (int mf = 0; mf < 4; mf++) {
        int r0 = row0 + wm * 64 + mf * 16 + gID;
        int r1 = r0 + 8;
        float s0 = (r0 < n) ? g_dinv[r0] : 0.f;
        float s1 = (r1 < n) ? g_dinv[r1] : 0.f;
#pragma unroll
        for (int nf = 0; nf < 8; nf++) {
            int cc = wn * 64 + nf * 8 + 2 * tig;
            if (r0 < n)
                *reinterpret_cast<float2*>(g_h + (size_t)r0 * HIDDEN + cc) =
                    make_float2(acc[mf][nf][0] * s0, acc[mf][nf][1] * s0);
            if (r1 < n)
                *reinterpret_cast<float2*>(g_h + (size_t)r1 * HIDDEN + cc) =
                    make_float2(acc[mf][nf][2] * s1, acc[mf][nf][3] * s1);
        }
    }
}

// ---------------------------------------------------------------------------
// launch #5: CSR fill
// ---------------------------------------------------------------------------
__global__ void k_fill(const int* __restrict__ src, const int* __restrict__ dst, int E) {
    int e = blockIdx.x * blockDim.x + threadIdx.x;
    if (e < E) {
        int d = dst[e];
        int pos = atomicAdd(&g_cur[d], 1);
        g_csr[pos] = src[e];
    }
}

// ---------------------------------------------------------------------------
// launch #6: fused aggregate + finalize (warp per node)
// ---------------------------------------------------------------------------
__global__ __launch_bounds__(256) void k_aggfinal(const float* __restrict__ b1,
                                                  const float* __restrict__ W2,
                                                  const float* __restrict__ b2,
                                                  float* __restrict__ out,
                                                  int n) {
    __shared__ float sW2[HIDDEN * N_CLASSES];
    __shared__ float sb1[HIDDEN];
    for (int i = threadIdx.x; i < HIDDEN * N_CLASSES; i += blockDim.x) sW2[i] = W2[i];
    for (int i = threadIdx.x; i < HIDDEN; i += blockDim.x) sb1[i] = b1[i];
    __syncthreads();

    const int warp = (blockIdx.x * blockDim.x + threadIdx.x) >> 5;
    const int lane = threadIdx.x & 31;
    if (warp >= n) return;

    const int beg = g_off[warp];
    const int end = g_off[warp + 1];
    const float* hrow = g_h + (size_t)warp * HIDDEN;

    float4 a0 = *reinterpret_cast<const float4*>(hrow + lane * 4);
    float4 a1 = *reinterpret_cast<const float4*>(hrow + 128 + lane * 4);

    int i = beg;
    for (; i + 3 < end; i += 4) {
        int s0 = __ldg(&g_csr[i]);
        int s1 = __ldg(&g_csr[i + 1]);
        int s2 = __ldg(&g_csr[i + 2]);
        int s3 = __ldg(&g_csr[i + 3]);
        const float* r0 = g_h + (size_t)s0 * HIDDEN;
        const float* r1 = g_h + (size_t)s1 * HIDDEN;
        const float* r2 = g_h + (size_t)s2 * HIDDEN;
        const float* r3 = g_h + (size_t)s3 * HIDDEN;
        float4 v00 = *reinterpret_cast<const float4*>(r0 + lane * 4);
        float4 v01 = *reinterpret_cast<const float4*>(r0 + 128 + lane * 4);
        float4 v10 = *reinterpret_cast<const float4*>(r1 + lane * 4);
        float4 v11 = *reinterpret_cast<const float4*>(r1 + 128 + lane * 4);
        float4 v20 = *reinterpret_cast<const float4*>(r2 + lane * 4);
        float4 v21 = *reinterpret_cast<const float4*>(r2 + 128 + lane * 4);
        float4 v30 = *reinterpret_cast<const float4*>(r3 + lane * 4);
        float4 v31 = *reinterpret_cast<const float4*>(r3 + 128 + lane * 4);
        a0.x += (v00.x + v10.x) + (v20.x + v30.x);
        a0.y += (v00.y + v10.y) + (v20.y + v30.y);
        a0.z += (v00.z + v10.z) + (v20.z + v30.z);
        a0.w += (v00.w + v10.w) + (v20.w + v30.w);
        a1.x += (v01.x + v11.x) + (v21.x + v31.x);
        a1.y += (v01.y + v11.y) + (v21.y + v31.y);
        a1.z += (v01.z + v11.z) + (v21.z + v31.z);
        a1.w += (v01.w + v11.w) + (v21.w + v31.w);
    }
    for (; i < end; i++) {
        int s0 = __ldg(&g_csr[i]);
        const float* r0 = g_h + (size_t)s0 * HIDDEN;
        float4 v00 = *reinterpret_cast<const float4*>(r0 + lane * 4);
        float4 v01 = *reinterpret_cast<const float4*>(r0 + 128 + lane * 4);
        a0.x += v00.x; a0.y += v00.y; a0.z += v00.z; a0.w += v00.w;
        a1.x += v01.x; a1.y += v01.y; a1.z += v01.z; a1.w += v01.w;
    }

    const float di = g_dinv[warp];
    float acc0 = 0.f, acc1 = 0.f, acc2 = 0.f;
    {
        const int c0 = lane * 4;
        float h;
        h = fmaxf(fmaf(di, a0.x, sb1[c0 + 0]), 0.f);
        acc0 += h * sW2[(c0 + 0) * 3 + 0]; acc1 += h * sW2[(c0 + 0) * 3 + 1]; acc2 += h * sW2[(c0 + 0) * 3 + 2];
        h = fmaxf(fmaf(di, a0.y, sb1[c0 + 1]), 0.f);
        acc0 += h * sW2[(c0 + 1) * 3 + 0]; acc1 += h * sW2[(c0 + 1) * 3 + 1]; acc2 += h * sW2[(c0 + 1) * 3 + 2];
        h = fmaxf(fmaf(di, a0.z, sb1[c0 + 2]), 0.f);
        acc0 += h * sW2[(c0 + 2) * 3 + 0]; acc1 += h * sW2[(c0 + 2) * 3 + 1]; acc2 += h * sW2[(c0 + 2) * 3 + 2];
        h = fmaxf(fmaf(di, a0.w, sb1[c0 + 3]), 0.f);
        acc0 += h * sW2[(c0 + 3) * 3 + 0]; acc1 += h * sW2[(c0 + 3) * 3 + 1]; acc2 += h * sW2[(c0 + 3) * 3 + 2];
        const int c1 = 128 + lane * 4;
        h = fmaxf(fmaf(di, a1.x, sb1[c1 + 0]), 0.f);
        acc0 += h * sW2[(c1 + 0) * 3 + 0]; acc1 += h * sW2[(c1 + 0) * 3 + 1]; acc2 += h * sW2[(c1 + 0) * 3 + 2];
        h = fmaxf(fmaf(di, a1.y, sb1[c1 + 1]), 0.f);
        acc0 += h * sW2[(c1 + 1) * 3 + 0]; acc1 += h * sW2[(c1 + 1) * 3 + 1]; acc2 += h * sW2[(c1 + 1) * 3 + 2];
        h = fmaxf(fmaf(di, a1.z, sb1[c1 + 2]), 0.f);
        acc0 += h * sW2[(c1 + 2) * 3 + 0]; acc1 += h * sW2[(c1 + 2) * 3 + 1]; acc2 += h * sW2[(c1 + 2) * 3 + 2];
        h = fmaxf(fmaf(di, a1.w, sb1[c1 + 3]), 0.f);
        acc0 += h * sW2[(c1 + 3) * 3 + 0]; acc1 += h * sW2[(c1 + 3) * 3 + 1]; acc2 += h * sW2[(c1 + 3) * 3 + 2];
    }
#pragma unroll
    for (int o = 16; o > 0; o >>= 1) {
        acc0 += __shfl_down_sync(0xFFFFFFFFu, acc0, o);
        acc1 += __shfl_down_sync(0xFFFFFFFFu, acc1, o);
        acc2 += __shfl_down_sync(0xFFFFFFFFu, acc2, o);
    }
    if (lane == 0) {
        float l0 = acc0 + b2[0];
        float l1 = acc1 + b2[1];
        float l2 = acc2 + b2[2];
        float m = fmaxf(l0, fmaxf(l1, l2));
        float se = expf(l0 - m) + expf(l1 - m) + expf(l2 - m);
        float lse = m + logf(se);
        out[(size_t)warp * 3 + 0] = l0 - lse;
        out[(size_t)warp * 3 + 1] = l1 - lse;
        out[(size_t)warp * 3 + 2] = l2 - lse;
    }
}

// ---------------------------------------------------------------------------
extern "C" void kernel_launch(void* const* d_in, const int* in_sizes, int n_in,
                              void* d_out, int out_size) {
    const float* x  = (const float*)d_in[0];
    const int*   ei = (const int*)d_in[1];
    const float* W1 = (const float*)d_in[2];
    const float* b1 = (const float*)d_in[3];
    const float* W2 = (const float*)d_in[4];
    const float* b2 = (const float*)d_in[5];
    float* out = (float*)d_out;

    int n = in_sizes[0] / IN_DIM;
    int E = in_sizes[1] / 2;
    const int* src = ei;
    const int* dst = ei + E;

    cudaFuncSetAttribute(k_gemm_hmma, cudaFuncAttributeMaxDynamicSharedMemorySize, GEMM_SMEM);

    // #1 prep W1 (+ zero cnt), #2 count, #3 scan (+dinv +cur)
    k_prep_w1<<<(IN_DIM * HIDDEN + 255) / 256, 256>>>(W1);
    k_cnt<<<(E + 255) / 256, 256>>>(dst, E);
    k_scan<<<1, 1024>>>(n);

    // #4 GEMM (profiled slot)
    k_gemm_hmma<<<(n + 127) / 128, 256, GEMM_SMEM>>>(x, n);

    // #5 CSR fill, #6 fused aggregate+finalize
    k_fill<<<(E + 255) / 256, 256>>>(src, dst, E);
    int fblocks = (n * 32 + 255) / 256;
    k_aggfinal<<<fblocks, 256>>>(b1, W2, b2, out, n);
}